// round 2
// baseline (speedup 1.0000x reference)
#include <cuda_runtime.h>
#include <cuda_bf16.h>
#include <math.h>

// Problem constants
#define BATCH 2
#define SEQ 2048
#define TOK (BATCH*SEQ)          // 4096
#define HID 3584
#define NH 32
#define NKV 4
#define HD 128
#define QD (NH*HD)               // 4096
#define KVD (NKV*HD)             // 512

// Scratch buffers (device globals: allocation-free)
__device__ float g_q[(size_t)TOK*QD];     // [t][h*128+d]
__device__ float g_k[(size_t)TOK*KVD];
__device__ float g_v[(size_t)TOK*KVD];
__device__ float g_attn[(size_t)TOK*QD];

// ---------------------------------------------------------------------------
// SGEMM NT: C[M,N] = A[M,K] * B[N,K]^T, all row-major fp32.
// 128x128 block tile, BK=16, 256 threads, 8x8 micro-tile, reg-prefetch of the
// next global tile to hide LDG latency behind the FMA chain.
// Assumes M%128==0, N%128==0, K%16==0 (true for all four calls).
// ---------------------------------------------------------------------------
__global__ void __launch_bounds__(256, 2)
sgemm_nt(const float* __restrict__ A, const float* __restrict__ B,
         float* __restrict__ C, int M, int N, int K)
{
    __shared__ float As[16][132];
    __shared__ float Bs[16][132];

    const int bm = blockIdx.y << 7;
    const int bn = blockIdx.x << 7;
    const int tid = threadIdx.x;
    const int tr = (tid >> 4) << 3;   // 0..120 step 8
    const int tc = (tid & 15) << 3;   // 0..120 step 8
    const int lrow = tid >> 2;        // 0..63
    const int lk   = (tid & 3) << 2;  // 0,4,8,12

    const float* Ap0 = A + (size_t)(bm + lrow) * K + lk;
    const float* Ap1 = Ap0 + (size_t)64 * K;
    const float* Bp0 = B + (size_t)(bn + lrow) * K + lk;
    const float* Bp1 = Bp0 + (size_t)64 * K;

    float4 ra0 = *(const float4*)Ap0;
    float4 ra1 = *(const float4*)Ap1;
    float4 rb0 = *(const float4*)Bp0;
    float4 rb1 = *(const float4*)Bp1;

    float acc[8][8];
    #pragma unroll
    for (int i = 0; i < 8; i++)
        #pragma unroll
        for (int j = 0; j < 8; j++) acc[i][j] = 0.f;

    const int KT = K >> 4;
    for (int kt = 0; kt < KT; kt++) {
        As[lk+0][lrow]    = ra0.x; As[lk+1][lrow]    = ra0.y;
        As[lk+2][lrow]    = ra0.z; As[lk+3][lrow]    = ra0.w;
        As[lk+0][lrow+64] = ra1.x; As[lk+1][lrow+64] = ra1.y;
        As[lk+2][lrow+64] = ra1.z; As[lk+3][lrow+64] = ra1.w;
        Bs[lk+0][lrow]    = rb0.x; Bs[lk+1][lrow]    = rb0.y;
        Bs[lk+2][lrow]    = rb0.z; Bs[lk+3][lrow]    = rb0.w;
        Bs[lk+0][lrow+64] = rb1.x; Bs[lk+1][lrow+64] = rb1.y;
        Bs[lk+2][lrow+64] = rb1.z; Bs[lk+3][lrow+64] = rb1.w;
        __syncthreads();

        if (kt + 1 < KT) {
            int off = (kt + 1) << 4;
            ra0 = *(const float4*)(Ap0 + off);
            ra1 = *(const float4*)(Ap1 + off);
            rb0 = *(const float4*)(Bp0 + off);
            rb1 = *(const float4*)(Bp1 + off);
        }

        #pragma unroll
        for (int kk = 0; kk < 16; kk++) {
            float a[8], b[8];
            *(float4*)&a[0] = *(const float4*)&As[kk][tr];
            *(float4*)&a[4] = *(const float4*)&As[kk][tr+4];
            *(float4*)&b[0] = *(const float4*)&Bs[kk][tc];
            *(float4*)&b[4] = *(const float4*)&Bs[kk][tc+4];
            #pragma unroll
            for (int i = 0; i < 8; i++)
                #pragma unroll
                for (int j = 0; j < 8; j++)
                    acc[i][j] = fmaf(a[i], b[j], acc[i][j]);
        }
        __syncthreads();
    }

    #pragma unroll
    for (int i = 0; i < 8; i++) {
        float* Cp = C + (size_t)(bm + tr + i) * N + bn + tc;
        *(float4*)Cp     = make_float4(acc[i][0], acc[i][1], acc[i][2], acc[i][3]);
        *(float4*)(Cp+4) = make_float4(acc[i][4], acc[i][5], acc[i][6], acc[i][7]);
    }
}

// ---------------------------------------------------------------------------
// RoPE in-place on [TOK][n_heads*128]; pairs (d, d+64), fp32 sincosf to match
// the JAX fp32 reference computation.
// Position ids: the dataset most likely holds int32 (JAX x64-disabled coerces
// jnp.int64 arange to int32), but we probe at runtime: for the arange data,
// word[1]==1 iff int32 layout, word[1]==0 iff little-endian int64 layout.
// ---------------------------------------------------------------------------
__global__ void rope_kernel(float* __restrict__ X, const int* __restrict__ pos32,
                            int n_heads, int total)
{
    int idx = blockIdx.x * 256 + threadIdx.x;
    if (idx >= total) return;
    int d  = idx & 63;
    int r  = idx >> 6;
    int hh = r % n_heads;
    int t  = r / n_heads;

    bool is64 = (pos32[1] == 0);               // int64 -> high word of elem 0
    int p = is64 ? pos32[2 * t] : pos32[t];    // low word holds the value

    float invf = powf(1.0e6f, -(float)d * (1.0f / 64.0f));
    float fr = (float)p * invf;
    float sv, cv;
    sincosf(fr, &sv, &cv);
    float* xp = X + (size_t)t * (n_heads * 128) + hh * 128 + d;
    float x1 = xp[0], x2 = xp[64];
    xp[0]  = x1 * cv - x2 * sv;
    xp[64] = x2 * cv + x1 * sv;
}

// ---------------------------------------------------------------------------
// Flash attention, fp32, non-causal. One block = (64 q-rows, head bh).
// Online softmax over 32 K-tiles of 64. 256 threads: (ty,tx)=16x16,
// scores 4x4/thread, PV acc 4x8/thread. 112KB dynamic smem.
// ---------------------------------------------------------------------------
__global__ void __launch_bounds__(256)
flash_attn(const float* __restrict__ Q, const float* __restrict__ K,
           const float* __restrict__ V, float* __restrict__ O)
{
    extern __shared__ float sm[];
    float* Qs = sm;            // [128][64] (d-major, transposed)
    float* Ks = sm + 8192;     // [128][64]
    float* Vs = sm + 16384;    // [64][128]
    float* Ps = sm + 24576;    // [64][64]

    const int bh  = blockIdx.y;
    const int b   = bh >> 5;
    const int h   = bh & 31;
    const int kvh = h >> 3;
    const int q0  = blockIdx.x << 6;
    const int tid = threadIdx.x;
    const int ty  = tid >> 4;
    const int tx  = tid & 15;
    const float scale = 0.08838834764831843f;  // 1/sqrt(128)

    // Load + transpose + prescale Q tile
    const float* Qb = Q + (size_t)(b * SEQ + q0) * QD + h * HD;
    #pragma unroll
    for (int i = 0; i < 8; i++) {
        int idx = tid + (i << 8);
        int row = idx >> 5;
        int d4  = (idx & 31) << 2;
        float4 qv = *(const float4*)(Qb + (size_t)row * QD + d4);
        Qs[(d4+0)*64 + row] = qv.x * scale;
        Qs[(d4+1)*64 + row] = qv.y * scale;
        Qs[(d4+2)*64 + row] = qv.z * scale;
        Qs[(d4+3)*64 + row] = qv.w * scale;
    }

    float m[4] = {-1e30f, -1e30f, -1e30f, -1e30f};
    float l[4] = {0.f, 0.f, 0.f, 0.f};
    float acc[4][8];
    #pragma unroll
    for (int i = 0; i < 4; i++)
        #pragma unroll
        for (int j = 0; j < 8; j++) acc[i][j] = 0.f;

    const float* Kb = K + (size_t)(b * SEQ) * KVD + kvh * HD;
    const float* Vb = V + (size_t)(b * SEQ) * KVD + kvh * HD;

    for (int kt = 0; kt < SEQ / 64; kt++) {
        __syncthreads();   // previous PV done with Vs/Ps
        #pragma unroll
        for (int i = 0; i < 8; i++) {
            int idx = tid + (i << 8);
            int j   = idx >> 5;
            int d4  = (idx & 31) << 2;
            size_t goff = (size_t)((kt << 6) + j) * KVD + d4;
            float4 kv = *(const float4*)(Kb + goff);
            Ks[(d4+0)*64 + j] = kv.x;
            Ks[(d4+1)*64 + j] = kv.y;
            Ks[(d4+2)*64 + j] = kv.z;
            Ks[(d4+3)*64 + j] = kv.w;
            *(float4*)&Vs[j * 128 + d4] = *(const float4*)(Vb + goff);
        }
        __syncthreads();

        // Scores: S = (Q*scale) K^T, 4x4 per thread
        float s[4][4];
        #pragma unroll
        for (int i = 0; i < 4; i++)
            #pragma unroll
            for (int j = 0; j < 4; j++) s[i][j] = 0.f;

        #pragma unroll 16
        for (int d = 0; d < 128; d++) {
            float4 aq = *(const float4*)&Qs[d * 64 + (ty << 2)];
            float4 bk = *(const float4*)&Ks[d * 64 + (tx << 2)];
            float a0 = aq.x, a1 = aq.y, a2 = aq.z, a3 = aq.w;
            float b0 = bk.x, b1 = bk.y, b2 = bk.z, b3 = bk.w;
            s[0][0] = fmaf(a0,b0,s[0][0]); s[0][1] = fmaf(a0,b1,s[0][1]);
            s[0][2] = fmaf(a0,b2,s[0][2]); s[0][3] = fmaf(a0,b3,s[0][3]);
            s[1][0] = fmaf(a1,b0,s[1][0]); s[1][1] = fmaf(a1,b1,s[1][1]);
            s[1][2] = fmaf(a1,b2,s[1][2]); s[1][3] = fmaf(a1,b3,s[1][3]);
            s[2][0] = fmaf(a2,b0,s[2][0]); s[2][1] = fmaf(a2,b1,s[2][1]);
            s[2][2] = fmaf(a2,b2,s[2][2]); s[2][3] = fmaf(a2,b3,s[2][3]);
            s[3][0] = fmaf(a3,b0,s[3][0]); s[3][1] = fmaf(a3,b1,s[3][1]);
            s[3][2] = fmaf(a3,b2,s[3][2]); s[3][3] = fmaf(a3,b3,s[3][3]);
        }

        // Online softmax per row (row stats reduced across the 16 tx lanes)
        #pragma unroll
        for (int i = 0; i < 4; i++) {
            float tm = fmaxf(fmaxf(s[i][0], s[i][1]), fmaxf(s[i][2], s[i][3]));
            tm = fmaxf(tm, __shfl_xor_sync(0xffffffffu, tm, 1));
            tm = fmaxf(tm, __shfl_xor_sync(0xffffffffu, tm, 2));
            tm = fmaxf(tm, __shfl_xor_sync(0xffffffffu, tm, 4));
            tm = fmaxf(tm, __shfl_xor_sync(0xffffffffu, tm, 8));
            float mn = fmaxf(m[i], tm);
            float alpha = expf(m[i] - mn);
            m[i] = mn;
            float rs = 0.f;
            #pragma unroll
            for (int j = 0; j < 4; j++) { s[i][j] = expf(s[i][j] - mn); rs += s[i][j]; }
            rs += __shfl_xor_sync(0xffffffffu, rs, 1);
            rs += __shfl_xor_sync(0xffffffffu, rs, 2);
            rs += __shfl_xor_sync(0xffffffffu, rs, 4);
            rs += __shfl_xor_sync(0xffffffffu, rs, 8);
            l[i] = l[i] * alpha + rs;
            #pragma unroll
            for (int j = 0; j < 8; j++) acc[i][j] *= alpha;
            *(float4*)&Ps[((ty << 2) + i) * 64 + (tx << 2)] =
                make_float4(s[i][0], s[i][1], s[i][2], s[i][3]);
        }
        __syncthreads();

        // PV: acc[64x128] += P[64x64] @ V[64x128]
        #pragma unroll 8
        for (int j = 0; j < 64; j++) {
            float4 v0 = *(const float4*)&Vs[j * 128 + (tx << 3)];
            float4 v1 = *(const float4*)&Vs[j * 128 + (tx << 3) + 4];
            #pragma unroll
            for (int i = 0; i < 4; i++) {
                float p = Ps[((ty << 2) + i) * 64 + j];
                acc[i][0] = fmaf(p, v0.x, acc[i][0]);
                acc[i][1] = fmaf(p, v0.y, acc[i][1]);
                acc[i][2] = fmaf(p, v0.z, acc[i][2]);
                acc[i][3] = fmaf(p, v0.w, acc[i][3]);
                acc[i][4] = fmaf(p, v1.x, acc[i][4]);
                acc[i][5] = fmaf(p, v1.y, acc[i][5]);
                acc[i][6] = fmaf(p, v1.z, acc[i][6]);
                acc[i][7] = fmaf(p, v1.w, acc[i][7]);
            }
        }
    }

    float* Ob = O + (size_t)(b * SEQ + q0) * QD + h * HD;
    #pragma unroll
    for (int i = 0; i < 4; i++) {
        float inv = 1.f / l[i];
        float* op = Ob + (size_t)((ty << 2) + i) * QD + (tx << 3);
        *(float4*)op     = make_float4(acc[i][0]*inv, acc[i][1]*inv, acc[i][2]*inv, acc[i][3]*inv);
        *(float4*)(op+4) = make_float4(acc[i][4]*inv, acc[i][5]*inv, acc[i][6]*inv, acc[i][7]*inv);
    }
}

// ---------------------------------------------------------------------------
extern "C" void kernel_launch(void* const* d_in, const int* in_sizes, int n_in,
                              void* d_out, int out_size)
{
    const float* hidden = (const float*)d_in[0];
    const int*   pos    = (const int*)d_in[1];   // int32 or int64 (probed on device)
    const float* Wq     = (const float*)d_in[2];
    const float* Wk     = (const float*)d_in[3];
    const float* Wv     = (const float*)d_in[4];
    const float* Wo     = (const float*)d_in[5];
    float*       out    = (float*)d_out;

    float *qb, *kb, *vb, *ab;
    cudaGetSymbolAddress((void**)&qb, g_q);
    cudaGetSymbolAddress((void**)&kb, g_k);
    cudaGetSymbolAddress((void**)&vb, g_v);
    cudaGetSymbolAddress((void**)&ab, g_attn);

    // Projections
    sgemm_nt<<<dim3(QD/128,  TOK/128), 256>>>(hidden, Wq, qb, TOK, QD,  HID);
    sgemm_nt<<<dim3(KVD/128, TOK/128), 256>>>(hidden, Wk, kb, TOK, KVD, HID);
    sgemm_nt<<<dim3(KVD/128, TOK/128), 256>>>(hidden, Wv, vb, TOK, KVD, HID);

    // RoPE on q and k
    rope_kernel<<<(TOK*NH*64 + 255)/256, 256>>>(qb, pos, NH,  TOK*NH*64);
    rope_kernel<<<(TOK*NKV*64 + 255)/256, 256>>>(kb, pos, NKV, TOK*NKV*64);

    // Attention
    cudaFuncSetAttribute(flash_attn, cudaFuncAttributeMaxDynamicSharedMemorySize, 114688);
    flash_attn<<<dim3(SEQ/64, BATCH*NH), 256, 114688>>>(qb, kb, vb, ab);

    // Output projection
    sgemm_nt<<<dim3(HID/128, TOK/128), 256>>>(ab, Wo, out, TOK, HID, QD);
}

// round 4
// speedup vs baseline: 1.3534x; 1.3534x over previous
#include <cuda_runtime.h>
#include <cuda_bf16.h>
#include <math.h>
#include <stdint.h>

// Problem constants
#define BATCH 2
#define SEQ 2048
#define TOK (BATCH*SEQ)          // 4096
#define HID 3584
#define NH 32
#define NKV 4
#define HD 128
#define QD (NH*HD)               // 4096
#define KVD (NKV*HD)             // 512

// fp32 scratch
__device__ float g_q[(size_t)TOK*QD];
__device__ float g_k[(size_t)TOK*KVD];
__device__ float g_v[(size_t)TOK*KVD];
__device__ float g_attn[(size_t)TOK*QD];
// split-bf16 scratch (hi/lo pairs)
__device__ __nv_bfloat16 g_hh[(size_t)TOK*HID],  g_hl[(size_t)TOK*HID];
__device__ __nv_bfloat16 g_wqh[(size_t)QD*HID],  g_wql[(size_t)QD*HID];
__device__ __nv_bfloat16 g_wkh[(size_t)KVD*HID], g_wkl[(size_t)KVD*HID];
__device__ __nv_bfloat16 g_wvh[(size_t)KVD*HID], g_wvl[(size_t)KVD*HID];
__device__ __nv_bfloat16 g_woh[(size_t)HID*QD],  g_wol[(size_t)HID*QD];
__device__ __nv_bfloat16 g_ah[(size_t)TOK*QD],   g_al[(size_t)TOK*QD];

// ===========================================================================
// PTX helpers (baseline ISA only: cp.async / ldmatrix / mma.sync)
// ===========================================================================
__device__ __forceinline__ uint32_t smem_u32(const void* p) {
    uint32_t a;
    asm("{ .reg .u64 t; cvta.to.shared.u64 t, %1; cvt.u32.u64 %0, t; }" : "=r"(a) : "l"(p));
    return a;
}
__device__ __forceinline__ void cp_async16(uint32_t dst, const void* src) {
    asm volatile("cp.async.cg.shared.global [%0], [%1], 16;" :: "r"(dst), "l"(src) : "memory");
}
#define CP_COMMIT() asm volatile("cp.async.commit_group;" ::: "memory")
#define CP_WAIT(n)  asm volatile("cp.async.wait_group %0;" :: "n"(n) : "memory")

__device__ __forceinline__ void ldm4(uint32_t* r, uint32_t addr) {
    asm volatile("ldmatrix.sync.aligned.m8n8.x4.shared.b16 {%0,%1,%2,%3}, [%4];"
                 : "=r"(r[0]), "=r"(r[1]), "=r"(r[2]), "=r"(r[3]) : "r"(addr));
}
__device__ __forceinline__ void mma_bf16(float* c, const uint32_t* a, const uint32_t* b) {
    asm volatile("mma.sync.aligned.m16n8k16.row.col.f32.bf16.bf16.f32 "
                 "{%0,%1,%2,%3}, {%4,%5,%6,%7}, {%8,%9}, {%0,%1,%2,%3};"
                 : "+f"(c[0]), "+f"(c[1]), "+f"(c[2]), "+f"(c[3])
                 : "r"(a[0]), "r"(a[1]), "r"(a[2]), "r"(a[3]), "r"(b[0]), "r"(b[1]));
}

// ===========================================================================
// split fp32 -> (hi, lo) bf16
// ===========================================================================
__global__ void split_bf16_kernel(const float* __restrict__ x,
                                  __nv_bfloat16* __restrict__ hi,
                                  __nv_bfloat16* __restrict__ lo, int n)
{
    int i = blockIdx.x * 256 + threadIdx.x;
    if (i >= n) return;
    float v = x[i];
    __nv_bfloat16 h = __float2bfloat16(v);
    hi[i] = h;
    lo[i] = __float2bfloat16(v - __bfloat162float(h));
}

// ===========================================================================
// mma.sync split-bf16 GEMM: C[M,N] = A[M,K] * B[N,K]^T, fp32-accurate.
// BM=128, BN=128, BK=32. 256 threads = 8 warps (2 rows x 4 cols),
// warp tile 64x32 = 4x4 m16n8k16 tiles. C = Ah*Bh + Ah*Bl + Al*Bh.
// cp.async double-buffered SMEM, 40-half row stride (ldmatrix conflict-free).
// Requires M%128==0, N%128==0, K%32==0.
// ===========================================================================
#define TSTR 40                       // halves per SMEM row
#define TILE_B (128*TSTR*2)           // bytes per tile = 10240
#define STAGE_B (4*TILE_B)            // Ah,Al,Bh,Bl = 40960
#define GEMM_SMEM (2*STAGE_B)         // 81920

__device__ __forceinline__ void gemm_issue_loads(
    uint32_t sstage, const __nv_bfloat16* pAh, const __nv_bfloat16* pAl,
    const __nv_bfloat16* pBh, const __nv_bfloat16* pBl, int K, int ko, int tid)
{
    #pragma unroll
    for (int i = 0; i < 2; i++) {
        int c = tid + (i << 8);            // 0..511
        int row = c >> 2;                  // 0..127
        int kc  = c & 3;                   // 16B chunk within 64B row
        uint32_t dst = (uint32_t)(row * TSTR + kc * 8) * 2;
        size_t src = (size_t)row * K + ko + kc * 8;
        cp_async16(sstage + 0*TILE_B + dst, pAh + src);
        cp_async16(sstage + 1*TILE_B + dst, pAl + src);
        cp_async16(sstage + 2*TILE_B + dst, pBh + src);
        cp_async16(sstage + 3*TILE_B + dst, pBl + src);
    }
}

__global__ void __launch_bounds__(256, 1)
gemm_bf16split(const __nv_bfloat16* __restrict__ Ah, const __nv_bfloat16* __restrict__ Al,
               const __nv_bfloat16* __restrict__ Bh, const __nv_bfloat16* __restrict__ Bl,
               float* __restrict__ C, int M, int N, int K)
{
    extern __shared__ char smem[];
    uint32_t sbase = smem_u32(smem);
    const int tid  = threadIdx.x;
    const int lane = tid & 31;
    const int wid  = tid >> 5;
    const int wm   = wid >> 2;     // 0..1
    const int wn   = wid & 3;      // 0..3
    const int bm = blockIdx.y << 7;
    const int bn = blockIdx.x << 7;

    const __nv_bfloat16* pAh = Ah + (size_t)bm * K;
    const __nv_bfloat16* pAl = Al + (size_t)bm * K;
    const __nv_bfloat16* pBh = Bh + (size_t)bn * K;
    const __nv_bfloat16* pBl = Bl + (size_t)bn * K;

    // lane-dependent ldmatrix byte offsets
    const uint32_t laneA = (uint32_t)((lane & 15) * TSTR + ((lane >> 4) << 3)) * 2;
    const uint32_t laneB = (uint32_t)(((lane & 7) + ((lane >> 4) << 3)) * TSTR
                                      + (((lane >> 3) & 1) << 3)) * 2;

    float acc[4][4][4];
    #pragma unroll
    for (int i = 0; i < 4; i++)
        #pragma unroll
        for (int j = 0; j < 4; j++)
            #pragma unroll
            for (int r = 0; r < 4; r++) acc[i][j][r] = 0.f;

    const int KT = K >> 5;
    gemm_issue_loads(sbase, pAh, pAl, pBh, pBl, K, 0, tid);
    CP_COMMIT();

    for (int kt = 0; kt < KT; kt++) {
        if (kt + 1 < KT) {
            gemm_issue_loads(sbase + ((kt + 1) & 1) * STAGE_B,
                             pAh, pAl, pBh, pBl, K, (kt + 1) << 5, tid);
            CP_COMMIT();
            CP_WAIT(1);
        } else {
            CP_WAIT(0);
        }
        __syncthreads();

        uint32_t st = sbase + (kt & 1) * STAGE_B;
        uint32_t sAh = st, sAl = st + TILE_B, sBh = st + 2*TILE_B, sBl = st + 3*TILE_B;

        #pragma unroll
        for (int kk = 0; kk < 2; kk++) {
            uint32_t ah[4][4], al[4][4];
            #pragma unroll
            for (int mi = 0; mi < 4; mi++) {
                uint32_t aoff = (uint32_t)(((wm * 64 + mi * 16) * TSTR + kk * 16) * 2);
                ldm4(ah[mi], sAh + aoff + laneA);
                ldm4(al[mi], sAl + aoff + laneA);
            }
            uint32_t bh[4][2], bl[4][2];
            #pragma unroll
            for (int nj2 = 0; nj2 < 2; nj2++) {
                uint32_t boff = (uint32_t)(((wn * 32 + nj2 * 16) * TSTR + kk * 16) * 2);
                uint32_t r[4];
                ldm4(r, sBh + boff + laneB);
                bh[nj2*2][0] = r[0]; bh[nj2*2][1] = r[1];
                bh[nj2*2+1][0] = r[2]; bh[nj2*2+1][1] = r[3];
                ldm4(r, sBl + boff + laneB);
                bl[nj2*2][0] = r[0]; bl[nj2*2][1] = r[1];
                bl[nj2*2+1][0] = r[2]; bl[nj2*2+1][1] = r[3];
            }
            #pragma unroll
            for (int mi = 0; mi < 4; mi++)
                #pragma unroll
                for (int nj = 0; nj < 4; nj++) {
                    mma_bf16(acc[mi][nj], ah[mi], bh[nj]);
                    mma_bf16(acc[mi][nj], ah[mi], bl[nj]);
                    mma_bf16(acc[mi][nj], al[mi], bh[nj]);
                }
        }
        __syncthreads();
    }

    // Epilogue: c0,c1 -> C[row][col..col+1]; c2,c3 -> C[row+8][col..col+1]
    const int g = lane >> 2, tg = lane & 3;
    #pragma unroll
    for (int mi = 0; mi < 4; mi++) {
        int row = bm + wm * 64 + mi * 16 + g;
        #pragma unroll
        for (int nj = 0; nj < 4; nj++) {
            int col = bn + wn * 32 + nj * 8 + tg * 2;
            float* p0 = C + (size_t)row * N + col;
            float* p1 = p0 + (size_t)8 * N;
            p0[0] = acc[mi][nj][0]; p0[1] = acc[mi][nj][1];
            p1[0] = acc[mi][nj][2]; p1[1] = acc[mi][nj][3];
        }
    }
}

// ---------------------------------------------------------------------------
// RoPE (fp32 sincosf). position_ids dtype probed on device (int32 vs int64).
// ---------------------------------------------------------------------------
__global__ void rope_kernel(float* __restrict__ X, const int* __restrict__ pos32,
                            int n_heads, int total)
{
    int idx = blockIdx.x * 256 + threadIdx.x;
    if (idx >= total) return;
    int d  = idx & 63;
    int r  = idx >> 6;
    int hh = r % n_heads;
    int t  = r / n_heads;
    bool is64 = (pos32[1] == 0);
    int p = is64 ? pos32[2 * t] : pos32[t];
    float invf = powf(1.0e6f, -(float)d * (1.0f / 64.0f));
    float fr = (float)p * invf;
    float sv, cv;
    sincosf(fr, &sv, &cv);
    float* xp = X + (size_t)t * (n_heads * 128) + hh * 128 + d;
    float x1 = xp[0], x2 = xp[64];
    xp[0]  = x1 * cv - x2 * sv;
    xp[64] = x2 * cv + x1 * sv;
}

// ---------------------------------------------------------------------------
// Flash attention, fp32, non-causal (unchanged from passing R2 kernel).
// ---------------------------------------------------------------------------
__global__ void __launch_bounds__(256)
flash_attn(const float* __restrict__ Q, const float* __restrict__ K,
           const float* __restrict__ V, float* __restrict__ O)
{
    extern __shared__ float sm[];
    float* Qs = sm;            // [128][64]
    float* Ks = sm + 8192;     // [128][64]
    float* Vs = sm + 16384;    // [64][128]
    float* Ps = sm + 24576;    // [64][64]

    const int bh  = blockIdx.y;
    const int b   = bh >> 5;
    const int h   = bh & 31;
    const int kvh = h >> 3;
    const int q0  = blockIdx.x << 6;
    const int tid = threadIdx.x;
    const int ty  = tid >> 4;
    const int tx  = tid & 15;
    const float scale = 0.08838834764831843f;

    const float* Qb = Q + (size_t)(b * SEQ + q0) * QD + h * HD;
    #pragma unroll
    for (int i = 0; i < 8; i++) {
        int idx = tid + (i << 8);
        int row = idx >> 5;
        int d4  = (idx & 31) << 2;
        float4 qv = *(const float4*)(Qb + (size_t)row * QD + d4);
        Qs[(d4+0)*64 + row] = qv.x * scale;
        Qs[(d4+1)*64 + row] = qv.y * scale;
        Qs[(d4+2)*64 + row] = qv.z * scale;
        Qs[(d4+3)*64 + row] = qv.w * scale;
    }

    float m[4] = {-1e30f, -1e30f, -1e30f, -1e30f};
    float l[4] = {0.f, 0.f, 0.f, 0.f};
    float acc[4][8];
    #pragma unroll
    for (int i = 0; i < 4; i++)
        #pragma unroll
        for (int j = 0; j < 8; j++) acc[i][j] = 0.f;

    const float* Kb = K + (size_t)(b * SEQ) * KVD + kvh * HD;
    const float* Vb = V + (size_t)(b * SEQ) * KVD + kvh * HD;

    for (int kt = 0; kt < SEQ / 64; kt++) {
        __syncthreads();
        #pragma unroll
        for (int i = 0; i < 8; i++) {
            int idx = tid + (i << 8);
            int j   = idx >> 5;
            int d4  = (idx & 31) << 2;
            size_t goff = (size_t)((kt << 6) + j) * KVD + d4;
            float4 kv = *(const float4*)(Kb + goff);
            Ks[(d4+0)*64 + j] = kv.x;
            Ks[(d4+1)*64 + j] = kv.y;
            Ks[(d4+2)*64 + j] = kv.z;
            Ks[(d4+3)*64 + j] = kv.w;
            *(float4*)&Vs[j * 128 + d4] = *(const float4*)(Vb + goff);
        }
        __syncthreads();

        float s[4][4];
        #pragma unroll
        for (int i = 0; i < 4; i++)
            #pragma unroll
            for (int j = 0; j < 4; j++) s[i][j] = 0.f;

        #pragma unroll 16
        for (int d = 0; d < 128; d++) {
            float4 aq = *(const float4*)&Qs[d * 64 + (ty << 2)];
            float4 bk = *(const float4*)&Ks[d * 64 + (tx << 2)];
            float a0 = aq.x, a1 = aq.y, a2 = aq.z, a3 = aq.w;
            float b0 = bk.x, b1 = bk.y, b2 = bk.z, b3 = bk.w;
            s[0][0] = fmaf(a0,b0,s[0][0]); s[0][1] = fmaf(a0,b1,s[0][1]);
            s[0][2] = fmaf(a0,b2,s[0][2]); s[0][3] = fmaf(a0,b3,s[0][3]);
            s[1][0] = fmaf(a1,b0,s[1][0]); s[1][1] = fmaf(a1,b1,s[1][1]);
            s[1][2] = fmaf(a1,b2,s[1][2]); s[1][3] = fmaf(a1,b3,s[1][3]);
            s[2][0] = fmaf(a2,b0,s[2][0]); s[2][1] = fmaf(a2,b1,s[2][1]);
            s[2][2] = fmaf(a2,b2,s[2][2]); s[2][3] = fmaf(a2,b3,s[2][3]);
            s[3][0] = fmaf(a3,b0,s[3][0]); s[3][1] = fmaf(a3,b1,s[3][1]);
            s[3][2] = fmaf(a3,b2,s[3][2]); s[3][3] = fmaf(a3,b3,s[3][3]);
        }

        #pragma unroll
        for (int i = 0; i < 4; i++) {
            float tm = fmaxf(fmaxf(s[i][0], s[i][1]), fmaxf(s[i][2], s[i][3]));
            tm = fmaxf(tm, __shfl_xor_sync(0xffffffffu, tm, 1));
            tm = fmaxf(tm, __shfl_xor_sync(0xffffffffu, tm, 2));
            tm = fmaxf(tm, __shfl_xor_sync(0xffffffffu, tm, 4));
            tm = fmaxf(tm, __shfl_xor_sync(0xffffffffu, tm, 8));
            float mn = fmaxf(m[i], tm);
            float alpha = expf(m[i] - mn);
            m[i] = mn;
            float rs = 0.f;
            #pragma unroll
            for (int j = 0; j < 4; j++) { s[i][j] = expf(s[i][j] - mn); rs += s[i][j]; }
            rs += __shfl_xor_sync(0xffffffffu, rs, 1);
            rs += __shfl_xor_sync(0xffffffffu, rs, 2);
            rs += __shfl_xor_sync(0xffffffffu, rs, 4);
            rs += __shfl_xor_sync(0xffffffffu, rs, 8);
            l[i] = l[i] * alpha + rs;
            #pragma unroll
            for (int j = 0; j < 8; j++) acc[i][j] *= alpha;
            *(float4*)&Ps[((ty << 2) + i) * 64 + (tx << 2)] =
                make_float4(s[i][0], s[i][1], s[i][2], s[i][3]);
        }
        __syncthreads();

        #pragma unroll 8
        for (int j = 0; j < 64; j++) {
            float4 v0 = *(const float4*)&Vs[j * 128 + (tx << 3)];
            float4 v1 = *(const float4*)&Vs[j * 128 + (tx << 3) + 4];
            #pragma unroll
            for (int i = 0; i < 4; i++) {
                float p = Ps[((ty << 2) + i) * 64 + j];
                acc[i][0] = fmaf(p, v0.x, acc[i][0]);
                acc[i][1] = fmaf(p, v0.y, acc[i][1]);
                acc[i][2] = fmaf(p, v0.z, acc[i][2]);
                acc[i][3] = fmaf(p, v0.w, acc[i][3]);
                acc[i][4] = fmaf(p, v1.x, acc[i][4]);
                acc[i][5] = fmaf(p, v1.y, acc[i][5]);
                acc[i][6] = fmaf(p, v1.z, acc[i][6]);
                acc[i][7] = fmaf(p, v1.w, acc[i][7]);
            }
        }
    }

    float* Ob = O + (size_t)(b * SEQ + q0) * QD + h * HD;
    #pragma unroll
    for (int i = 0; i < 4; i++) {
        float inv = 1.f / l[i];
        float* op = Ob + (size_t)((ty << 2) + i) * QD + (tx << 3);
        *(float4*)op     = make_float4(acc[i][0]*inv, acc[i][1]*inv, acc[i][2]*inv, acc[i][3]*inv);
        *(float4*)(op+4) = make_float4(acc[i][4]*inv, acc[i][5]*inv, acc[i][6]*inv, acc[i][7]*inv);
    }
}

// ---------------------------------------------------------------------------
extern "C" void kernel_launch(void* const* d_in, const int* in_sizes, int n_in,
                              void* d_out, int out_size)
{
    const float* hidden = (const float*)d_in[0];
    const int*   pos    = (const int*)d_in[1];
    const float* Wq     = (const float*)d_in[2];
    const float* Wk     = (const float*)d_in[3];
    const float* Wv     = (const float*)d_in[4];
    const float* Wo     = (const float*)d_in[5];
    float*       out    = (float*)d_out;

    float *qb, *kb, *vb, *ab;
    cudaGetSymbolAddress((void**)&qb, g_q);
    cudaGetSymbolAddress((void**)&kb, g_k);
    cudaGetSymbolAddress((void**)&vb, g_v);
    cudaGetSymbolAddress((void**)&ab, g_attn);
    __nv_bfloat16 *hh,*hl,*wqh,*wql,*wkh,*wkl,*wvh,*wvl,*woh,*wol,*ah,*al;
    cudaGetSymbolAddress((void**)&hh,  g_hh);  cudaGetSymbolAddress((void**)&hl,  g_hl);
    cudaGetSymbolAddress((void**)&wqh, g_wqh); cudaGetSymbolAddress((void**)&wql, g_wql);
    cudaGetSymbolAddress((void**)&wkh, g_wkh); cudaGetSymbolAddress((void**)&wkl, g_wkl);
    cudaGetSymbolAddress((void**)&wvh, g_wvh); cudaGetSymbolAddress((void**)&wvl, g_wvl);
    cudaGetSymbolAddress((void**)&woh, g_woh); cudaGetSymbolAddress((void**)&wol, g_wol);
    cudaGetSymbolAddress((void**)&ah,  g_ah);  cudaGetSymbolAddress((void**)&al,  g_al);

    cudaFuncSetAttribute(gemm_bf16split, cudaFuncAttributeMaxDynamicSharedMemorySize, GEMM_SMEM);
    cudaFuncSetAttribute(flash_attn, cudaFuncAttributeMaxDynamicSharedMemorySize, 114688);

    // Split inputs/weights into bf16 hi/lo
    split_bf16_kernel<<<(TOK*HID + 255)/256, 256>>>(hidden, hh, hl, TOK*HID);
    split_bf16_kernel<<<(QD*HID  + 255)/256, 256>>>(Wq, wqh, wql, QD*HID);
    split_bf16_kernel<<<(KVD*HID + 255)/256, 256>>>(Wk, wkh, wkl, KVD*HID);
    split_bf16_kernel<<<(KVD*HID + 255)/256, 256>>>(Wv, wvh, wvl, KVD*HID);
    split_bf16_kernel<<<(HID*QD  + 255)/256, 256>>>(Wo, woh, wol, HID*QD);

    // Projections on tensor cores (mma.sync split-bf16)
    gemm_bf16split<<<dim3(QD/128,  TOK/128), 256, GEMM_SMEM>>>(hh, hl, wqh, wql, qb, TOK, QD,  HID);
    gemm_bf16split<<<dim3(KVD/128, TOK/128), 256, GEMM_SMEM>>>(hh, hl, wkh, wkl, kb, TOK, KVD, HID);
    gemm_bf16split<<<dim3(KVD/128, TOK/128), 256, GEMM_SMEM>>>(hh, hl, wvh, wvl, vb, TOK, KVD, HID);

    // RoPE
    rope_kernel<<<(TOK*NH*64 + 255)/256, 256>>>(qb, pos, NH,  TOK*NH*64);
    rope_kernel<<<(TOK*NKV*64 + 255)/256, 256>>>(kb, pos, NKV, TOK*NKV*64);

    // Attention (fp32)
    flash_attn<<<dim3(SEQ/64, BATCH*NH), 256, 114688>>>(qb, kb, vb, ab);

    // Split attention output, then O-projection on tensor cores
    split_bf16_kernel<<<(TOK*QD + 255)/256, 256>>>(ab, ah, al, TOK*QD);
    gemm_bf16split<<<dim3(HID/128, TOK/128), 256, GEMM_SMEM>>>(ah, al, woh, wol, out, TOK, HID, QD);
}

// round 5
// speedup vs baseline: 3.0033x; 2.2190x over previous
#include <cuda_runtime.h>
#include <cuda_bf16.h>
#include <math.h>
#include <stdint.h>

// Problem constants
#define BATCH 2
#define SEQ 2048
#define TOK (BATCH*SEQ)          // 4096
#define HID 3584
#define NH 32
#define NKV 4
#define HD 128
#define QD (NH*HD)               // 4096
#define KVD (NKV*HD)             // 512

// fp32 scratch
__device__ float g_q[(size_t)TOK*QD];
__device__ float g_k[(size_t)TOK*KVD];
__device__ float g_v[(size_t)TOK*KVD];
__device__ float g_attn[(size_t)TOK*QD];
// split-bf16 scratch
__device__ __nv_bfloat16 g_hh[(size_t)TOK*HID],  g_hl[(size_t)TOK*HID];
__device__ __nv_bfloat16 g_wqh[(size_t)QD*HID],  g_wql[(size_t)QD*HID];
__device__ __nv_bfloat16 g_wkh[(size_t)KVD*HID], g_wkl[(size_t)KVD*HID];
__device__ __nv_bfloat16 g_wvh[(size_t)KVD*HID], g_wvl[(size_t)KVD*HID];
__device__ __nv_bfloat16 g_woh[(size_t)HID*QD],  g_wol[(size_t)HID*QD];
__device__ __nv_bfloat16 g_ah[(size_t)TOK*QD],   g_al[(size_t)TOK*QD];
// split K/V for attention (K roped)
__device__ __nv_bfloat16 g_kh[(size_t)TOK*KVD],  g_kl[(size_t)TOK*KVD];
__device__ __nv_bfloat16 g_vh[(size_t)TOK*KVD],  g_vl[(size_t)TOK*KVD];

// ===========================================================================
// PTX helpers (baseline ISA: cp.async / ldmatrix / mma.sync)
// ===========================================================================
__device__ __forceinline__ uint32_t smem_u32(const void* p) {
    uint32_t a;
    asm("{ .reg .u64 t; cvta.to.shared.u64 t, %1; cvt.u32.u64 %0, t; }" : "=r"(a) : "l"(p));
    return a;
}
__device__ __forceinline__ void cp_async16(uint32_t dst, const void* src) {
    asm volatile("cp.async.cg.shared.global [%0], [%1], 16;" :: "r"(dst), "l"(src) : "memory");
}
#define CP_COMMIT() asm volatile("cp.async.commit_group;" ::: "memory")
#define CP_WAIT(n)  asm volatile("cp.async.wait_group %0;" :: "n"(n) : "memory")

__device__ __forceinline__ void ldm4(uint32_t* r, uint32_t addr) {
    asm volatile("ldmatrix.sync.aligned.m8n8.x4.shared.b16 {%0,%1,%2,%3}, [%4];"
                 : "=r"(r[0]), "=r"(r[1]), "=r"(r[2]), "=r"(r[3]) : "r"(addr));
}
__device__ __forceinline__ void ldm4t(uint32_t* r, uint32_t addr) {
    asm volatile("ldmatrix.sync.aligned.m8n8.x4.trans.shared.b16 {%0,%1,%2,%3}, [%4];"
                 : "=r"(r[0]), "=r"(r[1]), "=r"(r[2]), "=r"(r[3]) : "r"(addr));
}
__device__ __forceinline__ void mma_bf16(float* c, const uint32_t* a, const uint32_t* b) {
    asm volatile("mma.sync.aligned.m16n8k16.row.col.f32.bf16.bf16.f32 "
                 "{%0,%1,%2,%3}, {%4,%5,%6,%7}, {%8,%9}, {%0,%1,%2,%3};"
                 : "+f"(c[0]), "+f"(c[1]), "+f"(c[2]), "+f"(c[3])
                 : "r"(a[0]), "r"(a[1]), "r"(a[2]), "r"(a[3]), "r"(b[0]), "r"(b[1]));
}
// d.hi = cvt(hi), d.lo = cvt(lo)
__device__ __forceinline__ uint32_t cvt2bf(float hi, float lo) {
    uint32_t r;
    asm("cvt.rn.bf16x2.f32 %0, %1, %2;" : "=r"(r) : "f"(hi), "f"(lo));
    return r;
}
__device__ __forceinline__ float bfloF(uint32_t p) { return __int_as_float(p << 16); }
__device__ __forceinline__ float bfhiF(uint32_t p) { return __int_as_float(p & 0xffff0000u); }

// fast 2^t on the FMA pipe (no MUFU); rel err ~2e-6 on the used range
__device__ __forceinline__ float fast_exp2(float t) {
    t = fmaxf(t, -120.0f);
    float r = t + 12582912.0f;             // 1.5*2^23: round-to-nearest-int
    float n = r - 12582912.0f;
    float f = t - n;                       // [-0.5, 0.5]
    int   ni = __float_as_int(r);          // low bits hold n
    float p = 1.3392112e-3f;
    p = fmaf(p, f, 9.6183463e-3f);
    p = fmaf(p, f, 5.5503277e-2f);
    p = fmaf(p, f, 2.4022652e-1f);
    p = fmaf(p, f, 6.9314718e-1f);
    p = fmaf(p, f, 1.0f);
    return __int_as_float(__float_as_int(p) + (ni << 23));
}

// ===========================================================================
// split fp32 -> (hi, lo) bf16
// ===========================================================================
__global__ void split_bf16_kernel(const float* __restrict__ x,
                                  __nv_bfloat16* __restrict__ hi,
                                  __nv_bfloat16* __restrict__ lo, int n)
{
    int i = blockIdx.x * 256 + threadIdx.x;
    if (i >= n) return;
    float v = x[i];
    __nv_bfloat16 h = __float2bfloat16(v);
    hi[i] = h;
    lo[i] = __float2bfloat16(v - __bfloat162float(h));
}

// ===========================================================================
// mma.sync split-bf16 GEMM (unchanged from passing R4 kernel)
// ===========================================================================
#define TSTR 40
#define TILE_B (128*TSTR*2)
#define STAGE_B (4*TILE_B)
#define GEMM_SMEM (2*STAGE_B)

__device__ __forceinline__ void gemm_issue_loads(
    uint32_t sstage, const __nv_bfloat16* pAh, const __nv_bfloat16* pAl,
    const __nv_bfloat16* pBh, const __nv_bfloat16* pBl, int K, int ko, int tid)
{
    #pragma unroll
    for (int i = 0; i < 2; i++) {
        int c = tid + (i << 8);
        int row = c >> 2;
        int kc  = c & 3;
        uint32_t dst = (uint32_t)(row * TSTR + kc * 8) * 2;
        size_t src = (size_t)row * K + ko + kc * 8;
        cp_async16(sstage + 0*TILE_B + dst, pAh + src);
        cp_async16(sstage + 1*TILE_B + dst, pAl + src);
        cp_async16(sstage + 2*TILE_B + dst, pBh + src);
        cp_async16(sstage + 3*TILE_B + dst, pBl + src);
    }
}

__global__ void __launch_bounds__(256, 1)
gemm_bf16split(const __nv_bfloat16* __restrict__ Ah, const __nv_bfloat16* __restrict__ Al,
               const __nv_bfloat16* __restrict__ Bh, const __nv_bfloat16* __restrict__ Bl,
               float* __restrict__ C, int M, int N, int K)
{
    extern __shared__ char smem[];
    uint32_t sbase = smem_u32(smem);
    const int tid  = threadIdx.x;
    const int lane = tid & 31;
    const int wid  = tid >> 5;
    const int wm   = wid >> 2;
    const int wn   = wid & 3;
    const int bm = blockIdx.y << 7;
    const int bn = blockIdx.x << 7;

    const __nv_bfloat16* pAh = Ah + (size_t)bm * K;
    const __nv_bfloat16* pAl = Al + (size_t)bm * K;
    const __nv_bfloat16* pBh = Bh + (size_t)bn * K;
    const __nv_bfloat16* pBl = Bl + (size_t)bn * K;

    const uint32_t laneA = (uint32_t)((lane & 15) * TSTR + ((lane >> 4) << 3)) * 2;
    const uint32_t laneB = (uint32_t)(((lane & 7) + ((lane >> 4) << 3)) * TSTR
                                      + (((lane >> 3) & 1) << 3)) * 2;

    float acc[4][4][4];
    #pragma unroll
    for (int i = 0; i < 4; i++)
        #pragma unroll
        for (int j = 0; j < 4; j++)
            #pragma unroll
            for (int r = 0; r < 4; r++) acc[i][j][r] = 0.f;

    const int KT = K >> 5;
    gemm_issue_loads(sbase, pAh, pAl, pBh, pBl, K, 0, tid);
    CP_COMMIT();

    for (int kt = 0; kt < KT; kt++) {
        if (kt + 1 < KT) {
            gemm_issue_loads(sbase + ((kt + 1) & 1) * STAGE_B,
                             pAh, pAl, pBh, pBl, K, (kt + 1) << 5, tid);
            CP_COMMIT();
            CP_WAIT(1);
        } else {
            CP_WAIT(0);
        }
        __syncthreads();

        uint32_t st = sbase + (kt & 1) * STAGE_B;
        uint32_t sAh = st, sAl = st + TILE_B, sBh = st + 2*TILE_B, sBl = st + 3*TILE_B;

        #pragma unroll
        for (int kk = 0; kk < 2; kk++) {
            uint32_t ah[4][4], al[4][4];
            #pragma unroll
            for (int mi = 0; mi < 4; mi++) {
                uint32_t aoff = (uint32_t)(((wm * 64 + mi * 16) * TSTR + kk * 16) * 2);
                ldm4(ah[mi], sAh + aoff + laneA);
                ldm4(al[mi], sAl + aoff + laneA);
            }
            uint32_t bh[4][2], bl[4][2];
            #pragma unroll
            for (int nj2 = 0; nj2 < 2; nj2++) {
                uint32_t boff = (uint32_t)(((wn * 32 + nj2 * 16) * TSTR + kk * 16) * 2);
                uint32_t r[4];
                ldm4(r, sBh + boff + laneB);
                bh[nj2*2][0] = r[0]; bh[nj2*2][1] = r[1];
                bh[nj2*2+1][0] = r[2]; bh[nj2*2+1][1] = r[3];
                ldm4(r, sBl + boff + laneB);
                bl[nj2*2][0] = r[0]; bl[nj2*2][1] = r[1];
                bl[nj2*2+1][0] = r[2]; bl[nj2*2+1][1] = r[3];
            }
            #pragma unroll
            for (int mi = 0; mi < 4; mi++)
                #pragma unroll
                for (int nj = 0; nj < 4; nj++) {
                    mma_bf16(acc[mi][nj], ah[mi], bh[nj]);
                    mma_bf16(acc[mi][nj], ah[mi], bl[nj]);
                    mma_bf16(acc[mi][nj], al[mi], bh[nj]);
                }
        }
        __syncthreads();
    }

    const int g = lane >> 2, tg = lane & 3;
    #pragma unroll
    for (int mi = 0; mi < 4; mi++) {
        int row = bm + wm * 64 + mi * 16 + g;
        #pragma unroll
        for (int nj = 0; nj < 4; nj++) {
            int col = bn + wn * 32 + nj * 8 + tg * 2;
            float* p0 = C + (size_t)row * N + col;
            float* p1 = p0 + (size_t)8 * N;
            p0[0] = acc[mi][nj][0]; p0[1] = acc[mi][nj][1];
            p1[0] = acc[mi][nj][2]; p1[1] = acc[mi][nj][3];
        }
    }
}

// ---------------------------------------------------------------------------
// RoPE on Q (fp32 in place). position_ids dtype probed (int32 vs int64).
// ---------------------------------------------------------------------------
__global__ void rope_kernel(float* __restrict__ X, const int* __restrict__ pos32,
                            int n_heads, int total)
{
    int idx = blockIdx.x * 256 + threadIdx.x;
    if (idx >= total) return;
    int d  = idx & 63;
    int r  = idx >> 6;
    int hh = r % n_heads;
    int t  = r / n_heads;
    bool is64 = (pos32[1] == 0);
    int p = is64 ? pos32[2 * t] : pos32[t];
    float invf = powf(1.0e6f, -(float)d * (1.0f / 64.0f));
    float fr = (float)p * invf;
    float sv, cv;
    sincosf(fr, &sv, &cv);
    float* xp = X + (size_t)t * (n_heads * 128) + hh * 128 + d;
    float x1 = xp[0], x2 = xp[64];
    xp[0]  = x1 * cv - x2 * sv;
    xp[64] = x2 * cv + x1 * sv;
}

// RoPE on K fused with hi/lo bf16 split (reads fp32 K, writes kh/kl only)
__global__ void rope_split_kernel(const float* __restrict__ X, const int* __restrict__ pos32,
                                  __nv_bfloat16* __restrict__ oh, __nv_bfloat16* __restrict__ ol,
                                  int n_heads, int total)
{
    int idx = blockIdx.x * 256 + threadIdx.x;
    if (idx >= total) return;
    int d  = idx & 63;
    int r  = idx >> 6;
    int hh = r % n_heads;
    int t  = r / n_heads;
    bool is64 = (pos32[1] == 0);
    int p = is64 ? pos32[2 * t] : pos32[t];
    float invf = powf(1.0e6f, -(float)d * (1.0f / 64.0f));
    float fr = (float)p * invf;
    float sv, cv;
    sincosf(fr, &sv, &cv);
    size_t off = (size_t)t * (n_heads * 128) + hh * 128 + d;
    float x1 = X[off], x2 = X[off + 64];
    float y1 = x1 * cv - x2 * sv;
    float y2 = x2 * cv + x1 * sv;
    __nv_bfloat16 h1 = __float2bfloat16(y1);
    __nv_bfloat16 h2 = __float2bfloat16(y2);
    oh[off]      = h1; ol[off]      = __float2bfloat16(y1 - __bfloat162float(h1));
    oh[off + 64] = h2; ol[off + 64] = __float2bfloat16(y2 - __bfloat162float(h2));
}

// ===========================================================================
// Flash attention v2: mma.sync split-bf16, FMA-pipe exp2, non-causal.
// Block = (128 q-rows, head). 8 warps, warp = 16 q-rows. Bk = 64.
// SMEM: Q hi/lo [128][136] halves + double-buffered K/V hi/lo [64][136].
// ===========================================================================
#define FSTR 136                          // halves per smem row (272B)
#define FA_Q_B (128*FSTR*2)               // 34816 bytes per Q component
#define FA_T_B (64*FSTR*2)                // 17408 bytes per KV tensor comp
#define FA_ST_B (4*FA_T_B)                // 69632 bytes per stage
#define FA_SMEM (2*FA_Q_B + 2*FA_ST_B)    // 208896

__device__ __forceinline__ void fa_load_kv(
    uint32_t stage, const __nv_bfloat16* __restrict__ Kh, const __nv_bfloat16* __restrict__ Kl,
    const __nv_bfloat16* __restrict__ Vh, const __nv_bfloat16* __restrict__ Vl,
    size_t rowbase, int kvoff, int tid)
{
    #pragma unroll
    for (int comp = 0; comp < 4; comp++) {
        const __nv_bfloat16* g = (comp == 0) ? Kh : (comp == 1) ? Kl : (comp == 2) ? Vh : Vl;
        #pragma unroll
        for (int jj = 0; jj < 4; jj++) {
            int cc = tid + (jj << 8);          // 0..1023
            int row = cc >> 4, kc = cc & 15;
            cp_async16(stage + comp * FA_T_B + (uint32_t)(row * 272 + kc * 16),
                       g + (rowbase + row) * KVD + kvoff + kc * 8);
        }
    }
}

__global__ void __launch_bounds__(256, 1)
flash_attn_mma(const float* __restrict__ Q,
               const __nv_bfloat16* __restrict__ Kh, const __nv_bfloat16* __restrict__ Kl,
               const __nv_bfloat16* __restrict__ Vh, const __nv_bfloat16* __restrict__ Vl,
               float* __restrict__ O)
{
    extern __shared__ char smem[];
    uint32_t sb = smem_u32(smem);
    const uint32_t sQH = sb;
    const uint32_t sQL = sb + FA_Q_B;
    const uint32_t sST = sb + 2 * FA_Q_B;

    const int tid = threadIdx.x, lane = tid & 31, w = tid >> 5;
    const int bh = blockIdx.y, b = bh >> 5, h = bh & 31, kvh = h >> 3;
    const int q0 = blockIdx.x << 7;
    const int g = lane >> 2, t = lane & 3;

    // --- Q load + scale(1/sqrt(d) * log2e) + hi/lo split into smem ---
    const float qsc = 0.08838834764831843f * 1.4426950408889634f;
    const float* Qg = Q + (size_t)(b * SEQ + q0) * QD + h * HD;
    #pragma unroll
    for (int i = 0; i < 16; i++) {
        int idx = tid + (i << 8);
        int row = idx >> 5, col = (idx & 31) << 2;
        float4 qv = *(const float4*)(Qg + (size_t)row * QD + col);
        float a0 = qv.x * qsc, a1 = qv.y * qsc, a2 = qv.z * qsc, a3 = qv.w * qsc;
        uint32_t h01 = cvt2bf(a1, a0);
        uint32_t h23 = cvt2bf(a3, a2);
        float r0 = a0 - bfloF(h01), r1 = a1 - bfhiF(h01);
        float r2 = a2 - bfloF(h23), r3 = a3 - bfhiF(h23);
        uint32_t l01 = cvt2bf(r1, r0);
        uint32_t l23 = cvt2bf(r3, r2);
        uint32_t doff = (uint32_t)(row * 272 + col * 2);
        *(uint2*)(smem + (sQH - sb) + doff) = make_uint2(h01, h23);
        *(uint2*)(smem + (sQL - sb) + doff) = make_uint2(l01, l23);
    }

    // accumulators
    float m0 = -1e30f, m1 = -1e30f, l0 = 0.f, l1 = 0.f;
    float o[16][4];
    #pragma unroll
    for (int nd = 0; nd < 16; nd++)
        #pragma unroll
        for (int c = 0; c < 4; c++) o[nd][c] = 0.f;

    const size_t kvbase = (size_t)b * SEQ;
    const int kvoff = kvh * HD;

    // ldmatrix lane addresses
    const uint32_t lA = (uint32_t)(((lane & 15) * FSTR + ((lane >> 4) << 3)) * 2);
    const uint32_t lB = (uint32_t)((((lane & 7) + ((lane >> 4) << 3)) * FSTR
                                    + (((lane >> 3) & 1) << 3)) * 2);
    const uint32_t lV = (uint32_t)((((lane & 7) + (((lane >> 3) & 1) << 3)) * FSTR
                                    + (((lane >> 4) & 1) << 3)) * 2);

    fa_load_kv(sST, Kh, Kl, Vh, Vl, kvbase, kvoff, tid);
    CP_COMMIT();

    for (int kt = 0; kt < SEQ / 64; kt++) {
        if (kt + 1 < SEQ / 64) {
            fa_load_kv(sST + ((kt + 1) & 1) * FA_ST_B, Kh, Kl, Vh, Vl,
                       kvbase + (size_t)(kt + 1) * 64, kvoff, tid);
            CP_COMMIT();
            CP_WAIT(1);
        } else {
            CP_WAIT(0);
        }
        __syncthreads();

        const uint32_t st = sST + (kt & 1) * FA_ST_B;
        const uint32_t sKH = st, sKL = st + FA_T_B, sVH = st + 2*FA_T_B, sVL = st + 3*FA_T_B;

        // ---- S = Qh*Kh' + Qh*Kl' + Ql*Kh' (scores in log2 units) ----
        float s[8][4];
        #pragma unroll
        for (int j = 0; j < 8; j++)
            #pragma unroll
            for (int c = 0; c < 4; c++) s[j][c] = 0.f;

        #pragma unroll
        for (int kk = 0; kk < 8; kk++) {
            uint32_t qh[4], ql[4];
            uint32_t qoff = (uint32_t)((w * 16 * FSTR + kk * 16) * 2);
            ldm4(qh, sQH + qoff + lA);
            ldm4(ql, sQL + qoff + lA);
            #pragma unroll
            for (int nj2 = 0; nj2 < 4; nj2++) {
                uint32_t koff = (uint32_t)((nj2 * 16 * FSTR + kk * 16) * 2);
                uint32_t rh[4], rl[4];
                ldm4(rh, sKH + koff + lB);
                ldm4(rl, sKL + koff + lB);
                mma_bf16(s[nj2*2],   qh, rh);     mma_bf16(s[nj2*2],   qh, rl);
                mma_bf16(s[nj2*2],   ql, rh);
                mma_bf16(s[nj2*2+1], qh, rh + 2); mma_bf16(s[nj2*2+1], qh, rl + 2);
                mma_bf16(s[nj2*2+1], ql, rh + 2);
            }
        }

        // ---- online softmax (base-2, poly exp2 on FMA pipe) ----
        float mx0 = -1e30f, mx1 = -1e30f;
        #pragma unroll
        for (int j = 0; j < 8; j++) {
            mx0 = fmaxf(mx0, fmaxf(s[j][0], s[j][1]));
            mx1 = fmaxf(mx1, fmaxf(s[j][2], s[j][3]));
        }
        mx0 = fmaxf(mx0, __shfl_xor_sync(0xffffffffu, mx0, 1));
        mx0 = fmaxf(mx0, __shfl_xor_sync(0xffffffffu, mx0, 2));
        mx1 = fmaxf(mx1, __shfl_xor_sync(0xffffffffu, mx1, 1));
        mx1 = fmaxf(mx1, __shfl_xor_sync(0xffffffffu, mx1, 2));
        float mn0 = fmaxf(m0, mx0), mn1 = fmaxf(m1, mx1);
        float al0 = fast_exp2(m0 - mn0), al1 = fast_exp2(m1 - mn1);
        m0 = mn0; m1 = mn1;

        uint32_t ph[4][4], pl[4][4];
        float sum0 = 0.f, sum1 = 0.f;
        #pragma unroll
        for (int j = 0; j < 8; j++) {
            float p00 = fast_exp2(s[j][0] - mn0);
            float p01 = fast_exp2(s[j][1] - mn0);
            float p10 = fast_exp2(s[j][2] - mn1);
            float p11 = fast_exp2(s[j][3] - mn1);
            sum0 += p00 + p01; sum1 += p10 + p11;
            uint32_t hA = cvt2bf(p01, p00);
            uint32_t hB = cvt2bf(p11, p10);
            uint32_t lAp = cvt2bf(p01 - bfhiF(hA), p00 - bfloF(hA));
            uint32_t lBp = cvt2bf(p11 - bfhiF(hB), p10 - bfloF(hB));
            int kk2 = j >> 1, hf = (j & 1) << 1;
            ph[kk2][hf]     = hA; ph[kk2][hf + 1] = hB;
            pl[kk2][hf]     = lAp; pl[kk2][hf + 1] = lBp;
        }
        sum0 += __shfl_xor_sync(0xffffffffu, sum0, 1);
        sum0 += __shfl_xor_sync(0xffffffffu, sum0, 2);
        sum1 += __shfl_xor_sync(0xffffffffu, sum1, 1);
        sum1 += __shfl_xor_sync(0xffffffffu, sum1, 2);
        l0 = l0 * al0 + sum0;
        l1 = l1 * al1 + sum1;
        #pragma unroll
        for (int nd = 0; nd < 16; nd++) {
            o[nd][0] *= al0; o[nd][1] *= al0;
            o[nd][2] *= al1; o[nd][3] *= al1;
        }

        // ---- O += Ph*Vh + Ph*Vl + Pl*Vh (V via ldmatrix.trans) ----
        #pragma unroll
        for (int kk2 = 0; kk2 < 4; kk2++) {
            #pragma unroll
            for (int ndp = 0; ndp < 8; ndp++) {
                uint32_t voff = (uint32_t)((kk2 * 16 * FSTR + ndp * 16) * 2);
                uint32_t vh[4], vl[4];
                ldm4t(vh, sVH + voff + lV);
                ldm4t(vl, sVL + voff + lV);
                mma_bf16(o[ndp*2],   ph[kk2], vh);     mma_bf16(o[ndp*2],   ph[kk2], vl);
                mma_bf16(o[ndp*2],   pl[kk2], vh);
                mma_bf16(o[ndp*2+1], ph[kk2], vh + 2); mma_bf16(o[ndp*2+1], ph[kk2], vl + 2);
                mma_bf16(o[ndp*2+1], pl[kk2], vh + 2);
            }
        }
        __syncthreads();   // all warps done with this stage before it is refilled
    }

    // ---- epilogue ----
    float il0 = 1.f / l0, il1 = 1.f / l1;
    float* Og = O + (size_t)(b * SEQ + q0 + w * 16 + g) * QD + h * HD;
    #pragma unroll
    for (int nd = 0; nd < 16; nd++) {
        int col = nd * 8 + t * 2;
        *(float2*)(Og + col)              = make_float2(o[nd][0] * il0, o[nd][1] * il0);
        *(float2*)(Og + (size_t)8 * QD + col) = make_float2(o[nd][2] * il1, o[nd][3] * il1);
    }
}

// ---------------------------------------------------------------------------
extern "C" void kernel_launch(void* const* d_in, const int* in_sizes, int n_in,
                              void* d_out, int out_size)
{
    const float* hidden = (const float*)d_in[0];
    const int*   pos    = (const int*)d_in[1];
    const float* Wq     = (const float*)d_in[2];
    const float* Wk     = (const float*)d_in[3];
    const float* Wv     = (const float*)d_in[4];
    const float* Wo     = (const float*)d_in[5];
    float*       out    = (float*)d_out;

    float *qb, *kb, *vb, *ab;
    cudaGetSymbolAddress((void**)&qb, g_q);
    cudaGetSymbolAddress((void**)&kb, g_k);
    cudaGetSymbolAddress((void**)&vb, g_v);
    cudaGetSymbolAddress((void**)&ab, g_attn);
    __nv_bfloat16 *hh,*hl,*wqh,*wql,*wkh,*wkl,*wvh,*wvl,*woh,*wol,*ah,*al,*kh,*kl,*vh,*vl;
    cudaGetSymbolAddress((void**)&hh,  g_hh);  cudaGetSymbolAddress((void**)&hl,  g_hl);
    cudaGetSymbolAddress((void**)&wqh, g_wqh); cudaGetSymbolAddress((void**)&wql, g_wql);
    cudaGetSymbolAddress((void**)&wkh, g_wkh); cudaGetSymbolAddress((void**)&wkl, g_wkl);
    cudaGetSymbolAddress((void**)&wvh, g_wvh); cudaGetSymbolAddress((void**)&wvl, g_wvl);
    cudaGetSymbolAddress((void**)&woh, g_woh); cudaGetSymbolAddress((void**)&wol, g_wol);
    cudaGetSymbolAddress((void**)&ah,  g_ah);  cudaGetSymbolAddress((void**)&al,  g_al);
    cudaGetSymbolAddress((void**)&kh,  g_kh);  cudaGetSymbolAddress((void**)&kl,  g_kl);
    cudaGetSymbolAddress((void**)&vh,  g_vh);  cudaGetSymbolAddress((void**)&vl,  g_vl);

    cudaFuncSetAttribute(gemm_bf16split, cudaFuncAttributeMaxDynamicSharedMemorySize, GEMM_SMEM);
    cudaFuncSetAttribute(flash_attn_mma, cudaFuncAttributeMaxDynamicSharedMemorySize, FA_SMEM);

    // Split inputs/weights into bf16 hi/lo
    split_bf16_kernel<<<(TOK*HID + 255)/256, 256>>>(hidden, hh, hl, TOK*HID);
    split_bf16_kernel<<<(QD*HID  + 255)/256, 256>>>(Wq, wqh, wql, QD*HID);
    split_bf16_kernel<<<(KVD*HID + 255)/256, 256>>>(Wk, wkh, wkl, KVD*HID);
    split_bf16_kernel<<<(KVD*HID + 255)/256, 256>>>(Wv, wvh, wvl, KVD*HID);
    split_bf16_kernel<<<(HID*QD  + 255)/256, 256>>>(Wo, woh, wol, HID*QD);

    // Projections (tensor cores)
    gemm_bf16split<<<dim3(QD/128,  TOK/128), 256, GEMM_SMEM>>>(hh, hl, wqh, wql, qb, TOK, QD,  HID);
    gemm_bf16split<<<dim3(KVD/128, TOK/128), 256, GEMM_SMEM>>>(hh, hl, wkh, wkl, kb, TOK, KVD, HID);
    gemm_bf16split<<<dim3(KVD/128, TOK/128), 256, GEMM_SMEM>>>(hh, hl, wvh, wvl, vb, TOK, KVD, HID);

    // RoPE: Q in-place fp32; K fused rope+split; V plain split
    rope_kernel<<<(TOK*NH*64 + 255)/256, 256>>>(qb, pos, NH, TOK*NH*64);
    rope_split_kernel<<<(TOK*NKV*64 + 255)/256, 256>>>(kb, pos, kh, kl, NKV, TOK*NKV*64);
    split_bf16_kernel<<<((size_t)TOK*KVD + 255)/256, 256>>>(vb, vh, vl, TOK*KVD);

    // Flash attention on tensor cores
    flash_attn_mma<<<dim3(SEQ/128, BATCH*NH), 256, FA_SMEM>>>(qb, kh, kl, vh, vl, ab);

    // O projection
    split_bf16_kernel<<<(TOK*QD + 255)/256, 256>>>(ab, ah, al, TOK*QD);
    gemm_bf16split<<<dim3(HID/128, TOK/128), 256, GEMM_SMEM>>>(ah, al, woh, wol, out, TOK, HID, QD);
}

// round 6
// speedup vs baseline: 3.3867x; 1.1277x over previous
#include <cuda_runtime.h>
#include <cuda_bf16.h>
#include <math.h>
#include <stdint.h>

// Problem constants
#define BATCH 2
#define SEQ 2048
#define TOK (BATCH*SEQ)          // 4096
#define HID 3584
#define NH 32
#define NKV 4
#define HD 128
#define QD (NH*HD)               // 4096
#define KVD (NKV*HD)             // 512

// fp32 scratch
__device__ float g_q[(size_t)TOK*QD];
__device__ float g_k[(size_t)TOK*KVD];
__device__ float g_v[(size_t)TOK*KVD];
// split-bf16 scratch
__device__ __nv_bfloat16 g_hh[(size_t)TOK*HID],  g_hl[(size_t)TOK*HID];
__device__ __nv_bfloat16 g_wqh[(size_t)QD*HID],  g_wql[(size_t)QD*HID];
__device__ __nv_bfloat16 g_wkh[(size_t)KVD*HID], g_wkl[(size_t)KVD*HID];
__device__ __nv_bfloat16 g_wvh[(size_t)KVD*HID], g_wvl[(size_t)KVD*HID];
__device__ __nv_bfloat16 g_woh[(size_t)HID*QD],  g_wol[(size_t)HID*QD];
__device__ __nv_bfloat16 g_ah[(size_t)TOK*QD],   g_al[(size_t)TOK*QD];
__device__ __nv_bfloat16 g_kh[(size_t)TOK*KVD],  g_kl[(size_t)TOK*KVD];
__device__ __nv_bfloat16 g_vh[(size_t)TOK*KVD],  g_vl[(size_t)TOK*KVD];

// ===========================================================================
// PTX helpers
// ===========================================================================
__device__ __forceinline__ uint32_t smem_u32(const void* p) {
    uint32_t a;
    asm("{ .reg .u64 t; cvta.to.shared.u64 t, %1; cvt.u32.u64 %0, t; }" : "=r"(a) : "l"(p));
    return a;
}
__device__ __forceinline__ void cp_async16(uint32_t dst, const void* src) {
    asm volatile("cp.async.cg.shared.global [%0], [%1], 16;" :: "r"(dst), "l"(src) : "memory");
}
#define CP_COMMIT() asm volatile("cp.async.commit_group;" ::: "memory")
#define CP_WAIT(n)  asm volatile("cp.async.wait_group %0;" :: "n"(n) : "memory")

__device__ __forceinline__ void ldm4(uint32_t* r, uint32_t addr) {
    asm volatile("ldmatrix.sync.aligned.m8n8.x4.shared.b16 {%0,%1,%2,%3}, [%4];"
                 : "=r"(r[0]), "=r"(r[1]), "=r"(r[2]), "=r"(r[3]) : "r"(addr));
}
__device__ __forceinline__ void ldm4t(uint32_t* r, uint32_t addr) {
    asm volatile("ldmatrix.sync.aligned.m8n8.x4.trans.shared.b16 {%0,%1,%2,%3}, [%4];"
                 : "=r"(r[0]), "=r"(r[1]), "=r"(r[2]), "=r"(r[3]) : "r"(addr));
}
__device__ __forceinline__ void mma_bf16(float* c, const uint32_t* a, const uint32_t* b) {
    asm volatile("mma.sync.aligned.m16n8k16.row.col.f32.bf16.bf16.f32 "
                 "{%0,%1,%2,%3}, {%4,%5,%6,%7}, {%8,%9}, {%0,%1,%2,%3};"
                 : "+f"(c[0]), "+f"(c[1]), "+f"(c[2]), "+f"(c[3])
                 : "r"(a[0]), "r"(a[1]), "r"(a[2]), "r"(a[3]), "r"(b[0]), "r"(b[1]));
}
__device__ __forceinline__ uint32_t cvt2bf(float hi, float lo) {
    uint32_t r;
    asm("cvt.rn.bf16x2.f32 %0, %1, %2;" : "=r"(r) : "f"(hi), "f"(lo));
    return r;
}
__device__ __forceinline__ float bfloF(uint32_t p) { return __int_as_float(p << 16); }
__device__ __forceinline__ float bfhiF(uint32_t p) { return __int_as_float(p & 0xffff0000u); }

// fast 2^t on the FMA pipe (no MUFU)
__device__ __forceinline__ float fast_exp2(float t) {
    t = fmaxf(t, -120.0f);
    float r = t + 12582912.0f;
    float n = r - 12582912.0f;
    float f = t - n;
    int   ni = __float_as_int(r);
    float p = 1.3392112e-3f;
    p = fmaf(p, f, 9.6183463e-3f);
    p = fmaf(p, f, 5.5503277e-2f);
    p = fmaf(p, f, 2.4022652e-1f);
    p = fmaf(p, f, 6.9314718e-1f);
    p = fmaf(p, f, 1.0f);
    return __int_as_float(__float_as_int(p) + (ni << 23));
}

// ===========================================================================
// split fp32 -> (hi, lo) bf16
// ===========================================================================
__global__ void split_bf16_kernel(const float* __restrict__ x,
                                  __nv_bfloat16* __restrict__ hi,
                                  __nv_bfloat16* __restrict__ lo, int n)
{
    int i = blockIdx.x * 256 + threadIdx.x;
    if (i >= n) return;
    float v = x[i];
    __nv_bfloat16 h = __float2bfloat16(v);
    hi[i] = h;
    lo[i] = __float2bfloat16(v - __bfloat162float(h));
}

// ===========================================================================
// mma.sync split-bf16 GEMM core: C[M,N] = A[M,K]*B[N,K]^T, 128x128x32 tiles,
// 4-stage cp.async pipeline, 8 warps (2x4), warp 64x32, 3-term split product.
// ===========================================================================
#define TSTR 40
#define TILE_B (128*TSTR*2)           // 10240
#define STAGE_B (4*TILE_B)            // 40960
#define GEMM_SMEM (4*STAGE_B)         // 163840, 4 stages

__device__ __forceinline__ void gemm_issue_loads(
    uint32_t sstage, const __nv_bfloat16* pAh, const __nv_bfloat16* pAl,
    const __nv_bfloat16* pBh, const __nv_bfloat16* pBl, int K, int ko, int tid)
{
    #pragma unroll
    for (int i = 0; i < 2; i++) {
        int c = tid + (i << 8);
        int row = c >> 2;
        int kc  = c & 3;
        uint32_t dst = (uint32_t)(row * TSTR + kc * 8) * 2;
        size_t src = (size_t)row * K + ko + kc * 8;
        cp_async16(sstage + 0*TILE_B + dst, pAh + src);
        cp_async16(sstage + 1*TILE_B + dst, pAl + src);
        cp_async16(sstage + 2*TILE_B + dst, pBh + src);
        cp_async16(sstage + 3*TILE_B + dst, pBl + src);
    }
}

__device__ __forceinline__ void gemm_core(
    const __nv_bfloat16* __restrict__ pAh, const __nv_bfloat16* __restrict__ pAl,
    const __nv_bfloat16* __restrict__ pBh, const __nv_bfloat16* __restrict__ pBl,
    float* __restrict__ Ct, int N, int K, char* smem)
{
    uint32_t sbase = smem_u32(smem);
    const int tid  = threadIdx.x;
    const int lane = tid & 31;
    const int wid  = tid >> 5;
    const int wm   = wid >> 2;
    const int wn   = wid & 3;

    const uint32_t laneA = (uint32_t)((lane & 15) * TSTR + ((lane >> 4) << 3)) * 2;
    const uint32_t laneB = (uint32_t)(((lane & 7) + ((lane >> 4) << 3)) * TSTR
                                      + (((lane >> 3) & 1) << 3)) * 2;

    float acc[4][4][4];
    #pragma unroll
    for (int i = 0; i < 4; i++)
        #pragma unroll
        for (int j = 0; j < 4; j++)
            #pragma unroll
            for (int r = 0; r < 4; r++) acc[i][j][r] = 0.f;

    const int KT = K >> 5;   // assumed >= 3
    #pragma unroll
    for (int i = 0; i < 3; i++) {
        gemm_issue_loads(sbase + i * STAGE_B, pAh, pAl, pBh, pBl, K, i << 5, tid);
        CP_COMMIT();
    }

    for (int kt = 0; kt < KT; kt++) {
        int rem = KT - 1 - kt;
        if (rem >= 2)      { CP_WAIT(2); }
        else if (rem == 1) { CP_WAIT(1); }
        else               { CP_WAIT(0); }
        __syncthreads();

        uint32_t st = sbase + (kt & 3) * STAGE_B;
        uint32_t sAh = st, sAl = st + TILE_B, sBh = st + 2*TILE_B, sBl = st + 3*TILE_B;

        #pragma unroll
        for (int kk = 0; kk < 2; kk++) {
            uint32_t ah[4][4], al[4][4];
            #pragma unroll
            for (int mi = 0; mi < 4; mi++) {
                uint32_t aoff = (uint32_t)(((wm * 64 + mi * 16) * TSTR + kk * 16) * 2);
                ldm4(ah[mi], sAh + aoff + laneA);
                ldm4(al[mi], sAl + aoff + laneA);
            }
            uint32_t bh[4][2], bl[4][2];
            #pragma unroll
            for (int nj2 = 0; nj2 < 2; nj2++) {
                uint32_t boff = (uint32_t)(((wn * 32 + nj2 * 16) * TSTR + kk * 16) * 2);
                uint32_t r[4];
                ldm4(r, sBh + boff + laneB);
                bh[nj2*2][0] = r[0]; bh[nj2*2][1] = r[1];
                bh[nj2*2+1][0] = r[2]; bh[nj2*2+1][1] = r[3];
                ldm4(r, sBl + boff + laneB);
                bl[nj2*2][0] = r[0]; bl[nj2*2][1] = r[1];
                bl[nj2*2+1][0] = r[2]; bl[nj2*2+1][1] = r[3];
            }
            #pragma unroll
            for (int mi = 0; mi < 4; mi++)
                #pragma unroll
                for (int nj = 0; nj < 4; nj++) {
                    mma_bf16(acc[mi][nj], ah[mi], bh[nj]);
                    mma_bf16(acc[mi][nj], ah[mi], bl[nj]);
                    mma_bf16(acc[mi][nj], al[mi], bh[nj]);
                }
        }

        if (kt + 3 < KT) {
            gemm_issue_loads(sbase + ((kt + 3) & 3) * STAGE_B,
                             pAh, pAl, pBh, pBl, K, (kt + 3) << 5, tid);
            CP_COMMIT();
        }
    }

    const int g = lane >> 2, tg = lane & 3;
    #pragma unroll
    for (int mi = 0; mi < 4; mi++) {
        int row = wm * 64 + mi * 16 + g;
        #pragma unroll
        for (int nj = 0; nj < 4; nj++) {
            int col = wn * 32 + nj * 8 + tg * 2;
            float* p0 = Ct + (size_t)row * N + col;
            float* p1 = p0 + (size_t)8 * N;
            p0[0] = acc[mi][nj][0]; p0[1] = acc[mi][nj][1];
            p1[0] = acc[mi][nj][2]; p1[1] = acc[mi][nj][3];
        }
    }
}

// Fused Q/K/V projection: grid (40, TOK/128). bx 0-31: Q; 32-35: K; 36-39: V.
__global__ void __launch_bounds__(256, 1)
gemm_qkv(const __nv_bfloat16* __restrict__ hh, const __nv_bfloat16* __restrict__ hl,
         const __nv_bfloat16* __restrict__ wqh, const __nv_bfloat16* __restrict__ wql,
         const __nv_bfloat16* __restrict__ wkh, const __nv_bfloat16* __restrict__ wkl,
         const __nv_bfloat16* __restrict__ wvh, const __nv_bfloat16* __restrict__ wvl,
         float* __restrict__ qb, float* __restrict__ kb, float* __restrict__ vb)
{
    extern __shared__ char smem[];
    const int bx = blockIdx.x;
    const int bm = blockIdx.y << 7;
    const __nv_bfloat16 *bhp, *blp;
    float* C; int bn, N;
    if (bx < 32)      { bhp = wqh; blp = wql; C = qb; bn = bx << 7;        N = QD;  }
    else if (bx < 36) { bhp = wkh; blp = wkl; C = kb; bn = (bx - 32) << 7; N = KVD; }
    else              { bhp = wvh; blp = wvl; C = vb; bn = (bx - 36) << 7; N = KVD; }
    gemm_core(hh + (size_t)bm * HID, hl + (size_t)bm * HID,
              bhp + (size_t)bn * HID, blp + (size_t)bn * HID,
              C + (size_t)bm * N + bn, N, HID, smem);
}

// Generic NT split GEMM (O-projection)
__global__ void __launch_bounds__(256, 1)
gemm_nt_split(const __nv_bfloat16* __restrict__ Ah, const __nv_bfloat16* __restrict__ Al,
              const __nv_bfloat16* __restrict__ Bh, const __nv_bfloat16* __restrict__ Bl,
              float* __restrict__ C, int N, int K)
{
    extern __shared__ char smem[];
    const int bm = blockIdx.y << 7;
    const int bn = blockIdx.x << 7;
    gemm_core(Ah + (size_t)bm * K, Al + (size_t)bm * K,
              Bh + (size_t)bn * K, Bl + (size_t)bn * K,
              C + (size_t)bm * N + bn, N, K, smem);
}

// ---------------------------------------------------------------------------
// RoPE on Q (fp32 in place). position_ids dtype probed (int32 vs int64).
// ---------------------------------------------------------------------------
__global__ void rope_kernel(float* __restrict__ X, const int* __restrict__ pos32,
                            int n_heads, int total)
{
    int idx = blockIdx.x * 256 + threadIdx.x;
    if (idx >= total) return;
    int d  = idx & 63;
    int r  = idx >> 6;
    int hh = r % n_heads;
    int t  = r / n_heads;
    bool is64 = (pos32[1] == 0);
    int p = is64 ? pos32[2 * t] : pos32[t];
    float invf = powf(1.0e6f, -(float)d * (1.0f / 64.0f));
    float fr = (float)p * invf;
    float sv, cv;
    sincosf(fr, &sv, &cv);
    float* xp = X + (size_t)t * (n_heads * 128) + hh * 128 + d;
    float x1 = xp[0], x2 = xp[64];
    xp[0]  = x1 * cv - x2 * sv;
    xp[64] = x2 * cv + x1 * sv;
}

// RoPE on K fused with hi/lo bf16 split
__global__ void rope_split_kernel(const float* __restrict__ X, const int* __restrict__ pos32,
                                  __nv_bfloat16* __restrict__ oh, __nv_bfloat16* __restrict__ ol,
                                  int n_heads, int total)
{
    int idx = blockIdx.x * 256 + threadIdx.x;
    if (idx >= total) return;
    int d  = idx & 63;
    int r  = idx >> 6;
    int hh = r % n_heads;
    int t  = r / n_heads;
    bool is64 = (pos32[1] == 0);
    int p = is64 ? pos32[2 * t] : pos32[t];
    float invf = powf(1.0e6f, -(float)d * (1.0f / 64.0f));
    float fr = (float)p * invf;
    float sv, cv;
    sincosf(fr, &sv, &cv);
    size_t off = (size_t)t * (n_heads * 128) + hh * 128 + d;
    float x1 = X[off], x2 = X[off + 64];
    float y1 = x1 * cv - x2 * sv;
    float y2 = x2 * cv + x1 * sv;
    __nv_bfloat16 h1 = __float2bfloat16(y1);
    __nv_bfloat16 h2 = __float2bfloat16(y2);
    oh[off]      = h1; ol[off]      = __float2bfloat16(y1 - __bfloat162float(h1));
    oh[off + 64] = h2; ol[off + 64] = __float2bfloat16(y2 - __bfloat162float(h2));
}

// ===========================================================================
// Flash attention: mma.sync split-bf16, FMA-pipe exp2, non-causal.
// Epilogue writes split bf16 hi/lo directly (feeds O-projection).
// ===========================================================================
#define FSTR 136
#define FA_Q_B (128*FSTR*2)
#define FA_T_B (64*FSTR*2)
#define FA_ST_B (4*FA_T_B)
#define FA_SMEM (2*FA_Q_B + 2*FA_ST_B)    // 208896

__device__ __forceinline__ void fa_load_kv(
    uint32_t stage, const __nv_bfloat16* __restrict__ Kh, const __nv_bfloat16* __restrict__ Kl,
    const __nv_bfloat16* __restrict__ Vh, const __nv_bfloat16* __restrict__ Vl,
    size_t rowbase, int kvoff, int tid)
{
    #pragma unroll
    for (int comp = 0; comp < 4; comp++) {
        const __nv_bfloat16* g = (comp == 0) ? Kh : (comp == 1) ? Kl : (comp == 2) ? Vh : Vl;
        #pragma unroll
        for (int jj = 0; jj < 4; jj++) {
            int cc = tid + (jj << 8);
            int row = cc >> 4, kc = cc & 15;
            cp_async16(stage + comp * FA_T_B + (uint32_t)(row * 272 + kc * 16),
                       g + (rowbase + row) * KVD + kvoff + kc * 8);
        }
    }
}

__global__ void __launch_bounds__(256, 1)
flash_attn_mma(const float* __restrict__ Q,
               const __nv_bfloat16* __restrict__ Kh, const __nv_bfloat16* __restrict__ Kl,
               const __nv_bfloat16* __restrict__ Vh, const __nv_bfloat16* __restrict__ Vl,
               __nv_bfloat16* __restrict__ ah, __nv_bfloat16* __restrict__ al)
{
    extern __shared__ char smem[];
    uint32_t sb = smem_u32(smem);
    const uint32_t sQH = sb;
    const uint32_t sQL = sb + FA_Q_B;
    const uint32_t sST = sb + 2 * FA_Q_B;

    const int tid = threadIdx.x, lane = tid & 31, w = tid >> 5;
    const int bh = blockIdx.y, b = bh >> 5, h = bh & 31, kvh = h >> 3;
    const int q0 = blockIdx.x << 7;
    const int g = lane >> 2, t = lane & 3;

    const float qsc = 0.08838834764831843f * 1.4426950408889634f;
    const float* Qg = Q + (size_t)(b * SEQ + q0) * QD + h * HD;
    #pragma unroll
    for (int i = 0; i < 16; i++) {
        int idx = tid + (i << 8);
        int row = idx >> 5, col = (idx & 31) << 2;
        float4 qv = *(const float4*)(Qg + (size_t)row * QD + col);
        float a0 = qv.x * qsc, a1 = qv.y * qsc, a2 = qv.z * qsc, a3 = qv.w * qsc;
        uint32_t h01 = cvt2bf(a1, a0);
        uint32_t h23 = cvt2bf(a3, a2);
        float r0 = a0 - bfloF(h01), r1 = a1 - bfhiF(h01);
        float r2 = a2 - bfloF(h23), r3 = a3 - bfhiF(h23);
        uint32_t l01 = cvt2bf(r1, r0);
        uint32_t l23 = cvt2bf(r3, r2);
        uint32_t doff = (uint32_t)(row * 272 + col * 2);
        *(uint2*)(smem + (sQH - sb) + doff) = make_uint2(h01, h23);
        *(uint2*)(smem + (sQL - sb) + doff) = make_uint2(l01, l23);
    }

    float m0 = -1e30f, m1 = -1e30f, l0 = 0.f, l1 = 0.f;
    float o[16][4];
    #pragma unroll
    for (int nd = 0; nd < 16; nd++)
        #pragma unroll
        for (int c = 0; c < 4; c++) o[nd][c] = 0.f;

    const size_t kvbase = (size_t)b * SEQ;
    const int kvoff = kvh * HD;

    const uint32_t lA = (uint32_t)(((lane & 15) * FSTR + ((lane >> 4) << 3)) * 2);
    const uint32_t lB = (uint32_t)((((lane & 7) + ((lane >> 4) << 3)) * FSTR
                                    + (((lane >> 3) & 1) << 3)) * 2);
    const uint32_t lV = (uint32_t)((((lane & 7) + (((lane >> 3) & 1) << 3)) * FSTR
                                    + (((lane >> 4) & 1) << 3)) * 2);

    fa_load_kv(sST, Kh, Kl, Vh, Vl, kvbase, kvoff, tid);
    CP_COMMIT();

    for (int kt = 0; kt < SEQ / 64; kt++) {
        if (kt + 1 < SEQ / 64) {
            fa_load_kv(sST + ((kt + 1) & 1) * FA_ST_B, Kh, Kl, Vh, Vl,
                       kvbase + (size_t)(kt + 1) * 64, kvoff, tid);
            CP_COMMIT();
            CP_WAIT(1);
        } else {
            CP_WAIT(0);
        }
        __syncthreads();

        const uint32_t st = sST + (kt & 1) * FA_ST_B;
        const uint32_t sKH = st, sKL = st + FA_T_B, sVH = st + 2*FA_T_B, sVL = st + 3*FA_T_B;

        float s[8][4];
        #pragma unroll
        for (int j = 0; j < 8; j++)
            #pragma unroll
            for (int c = 0; c < 4; c++) s[j][c] = 0.f;

        #pragma unroll
        for (int kk = 0; kk < 8; kk++) {
            uint32_t qh[4], ql[4];
            uint32_t qoff = (uint32_t)((w * 16 * FSTR + kk * 16) * 2);
            ldm4(qh, sQH + qoff + lA);
            ldm4(ql, sQL + qoff + lA);
            #pragma unroll
            for (int nj2 = 0; nj2 < 4; nj2++) {
                uint32_t koff = (uint32_t)((nj2 * 16 * FSTR + kk * 16) * 2);
                uint32_t rh[4], rl[4];
                ldm4(rh, sKH + koff + lB);
                ldm4(rl, sKL + koff + lB);
                mma_bf16(s[nj2*2],   qh, rh);     mma_bf16(s[nj2*2],   qh, rl);
                mma_bf16(s[nj2*2],   ql, rh);
                mma_bf16(s[nj2*2+1], qh, rh + 2); mma_bf16(s[nj2*2+1], qh, rl + 2);
                mma_bf16(s[nj2*2+1], ql, rh + 2);
            }
        }

        float mx0 = -1e30f, mx1 = -1e30f;
        #pragma unroll
        for (int j = 0; j < 8; j++) {
            mx0 = fmaxf(mx0, fmaxf(s[j][0], s[j][1]));
            mx1 = fmaxf(mx1, fmaxf(s[j][2], s[j][3]));
        }
        mx0 = fmaxf(mx0, __shfl_xor_sync(0xffffffffu, mx0, 1));
        mx0 = fmaxf(mx0, __shfl_xor_sync(0xffffffffu, mx0, 2));
        mx1 = fmaxf(mx1, __shfl_xor_sync(0xffffffffu, mx1, 1));
        mx1 = fmaxf(mx1, __shfl_xor_sync(0xffffffffu, mx1, 2));
        float mn0 = fmaxf(m0, mx0), mn1 = fmaxf(m1, mx1);
        float al0 = fast_exp2(m0 - mn0), al1 = fast_exp2(m1 - mn1);
        m0 = mn0; m1 = mn1;

        uint32_t ph[4][4], pl[4][4];
        float sum0 = 0.f, sum1 = 0.f;
        #pragma unroll
        for (int j = 0; j < 8; j++) {
            float p00 = fast_exp2(s[j][0] - mn0);
            float p01 = fast_exp2(s[j][1] - mn0);
            float p10 = fast_exp2(s[j][2] - mn1);
            float p11 = fast_exp2(s[j][3] - mn1);
            sum0 += p00 + p01; sum1 += p10 + p11;
            uint32_t hA = cvt2bf(p01, p00);
            uint32_t hB = cvt2bf(p11, p10);
            uint32_t lAp = cvt2bf(p01 - bfhiF(hA), p00 - bfloF(hA));
            uint32_t lBp = cvt2bf(p11 - bfhiF(hB), p10 - bfloF(hB));
            int kk2 = j >> 1, hf = (j & 1) << 1;
            ph[kk2][hf]     = hA;  ph[kk2][hf + 1] = hB;
            pl[kk2][hf]     = lAp; pl[kk2][hf + 1] = lBp;
        }
        sum0 += __shfl_xor_sync(0xffffffffu, sum0, 1);
        sum0 += __shfl_xor_sync(0xffffffffu, sum0, 2);
        sum1 += __shfl_xor_sync(0xffffffffu, sum1, 1);
        sum1 += __shfl_xor_sync(0xffffffffu, sum1, 2);
        l0 = l0 * al0 + sum0;
        l1 = l1 * al1 + sum1;
        #pragma unroll
        for (int nd = 0; nd < 16; nd++) {
            o[nd][0] *= al0; o[nd][1] *= al0;
            o[nd][2] *= al1; o[nd][3] *= al1;
        }

        #pragma unroll
        for (int kk2 = 0; kk2 < 4; kk2++) {
            #pragma unroll
            for (int ndp = 0; ndp < 8; ndp++) {
                uint32_t voff = (uint32_t)((kk2 * 16 * FSTR + ndp * 16) * 2);
                uint32_t vh[4], vl[4];
                ldm4t(vh, sVH + voff + lV);
                ldm4t(vl, sVL + voff + lV);
                mma_bf16(o[ndp*2],   ph[kk2], vh);     mma_bf16(o[ndp*2],   ph[kk2], vl);
                mma_bf16(o[ndp*2],   pl[kk2], vh);
                mma_bf16(o[ndp*2+1], ph[kk2], vh + 2); mma_bf16(o[ndp*2+1], ph[kk2], vl + 2);
                mma_bf16(o[ndp*2+1], pl[kk2], vh + 2);
            }
        }
        __syncthreads();
    }

    // epilogue: normalize + split to bf16 hi/lo directly
    float il0 = 1.f / l0, il1 = 1.f / l1;
    size_t rbase = (size_t)(b * SEQ + q0 + w * 16 + g) * QD + h * HD;
    __nv_bfloat16* AH = ah + rbase;
    __nv_bfloat16* AL = al + rbase;
    #pragma unroll
    for (int nd = 0; nd < 16; nd++) {
        int col = nd * 8 + t * 2;
        float a0 = o[nd][0] * il0, a1 = o[nd][1] * il0;
        uint32_t hp = cvt2bf(a1, a0);
        uint32_t lp = cvt2bf(a1 - bfhiF(hp), a0 - bfloF(hp));
        *(uint32_t*)(AH + col) = hp;
        *(uint32_t*)(AL + col) = lp;
        float b0 = o[nd][2] * il1, b1 = o[nd][3] * il1;
        hp = cvt2bf(b1, b0);
        lp = cvt2bf(b1 - bfhiF(hp), b0 - bfloF(hp));
        *(uint32_t*)(AH + (size_t)8 * QD + col) = hp;
        *(uint32_t*)(AL + (size_t)8 * QD + col) = lp;
    }
}

// ---------------------------------------------------------------------------
extern "C" void kernel_launch(void* const* d_in, const int* in_sizes, int n_in,
                              void* d_out, int out_size)
{
    const float* hidden = (const float*)d_in[0];
    const int*   pos    = (const int*)d_in[1];
    const float* Wq     = (const float*)d_in[2];
    const float* Wk     = (const float*)d_in[3];
    const float* Wv     = (const float*)d_in[4];
    const float* Wo     = (const float*)d_in[5];
    float*       out    = (float*)d_out;

    float *qb, *kb, *vb;
    cudaGetSymbolAddress((void**)&qb, g_q);
    cudaGetSymbolAddress((void**)&kb, g_k);
    cudaGetSymbolAddress((void**)&vb, g_v);
    __nv_bfloat16 *hh,*hl,*wqh,*wql,*wkh,*wkl,*wvh,*wvl,*woh,*wol,*ah,*al,*kh,*kl,*vh,*vl;
    cudaGetSymbolAddress((void**)&hh,  g_hh);  cudaGetSymbolAddress((void**)&hl,  g_hl);
    cudaGetSymbolAddress((void**)&wqh, g_wqh); cudaGetSymbolAddress((void**)&wql, g_wql);
    cudaGetSymbolAddress((void**)&wkh, g_wkh); cudaGetSymbolAddress((void**)&wkl, g_wkl);
    cudaGetSymbolAddress((void**)&wvh, g_wvh); cudaGetSymbolAddress((void**)&wvl, g_wvl);
    cudaGetSymbolAddress((void**)&woh, g_woh); cudaGetSymbolAddress((void**)&wol, g_wol);
    cudaGetSymbolAddress((void**)&ah,  g_ah);  cudaGetSymbolAddress((void**)&al,  g_al);
    cudaGetSymbolAddress((void**)&kh,  g_kh);  cudaGetSymbolAddress((void**)&kl,  g_kl);
    cudaGetSymbolAddress((void**)&vh,  g_vh);  cudaGetSymbolAddress((void**)&vl,  g_vl);

    cudaFuncSetAttribute(gemm_qkv, cudaFuncAttributeMaxDynamicSharedMemorySize, GEMM_SMEM);
    cudaFuncSetAttribute(gemm_nt_split, cudaFuncAttributeMaxDynamicSharedMemorySize, GEMM_SMEM);
    cudaFuncSetAttribute(flash_attn_mma, cudaFuncAttributeMaxDynamicSharedMemorySize, FA_SMEM);

    // Splits
    split_bf16_kernel<<<(TOK*HID + 255)/256, 256>>>(hidden, hh, hl, TOK*HID);
    split_bf16_kernel<<<(QD*HID  + 255)/256, 256>>>(Wq, wqh, wql, QD*HID);
    split_bf16_kernel<<<(KVD*HID + 255)/256, 256>>>(Wk, wkh, wkl, KVD*HID);
    split_bf16_kernel<<<(KVD*HID + 255)/256, 256>>>(Wv, wvh, wvl, KVD*HID);
    split_bf16_kernel<<<(HID*QD  + 255)/256, 256>>>(Wo, woh, wol, HID*QD);

    // Fused Q/K/V projections
    gemm_qkv<<<dim3(40, TOK/128), 256, GEMM_SMEM>>>(hh, hl, wqh, wql, wkh, wkl, wvh, wvl,
                                                    qb, kb, vb);

    // RoPE: Q in-place fp32; K fused rope+split; V plain split
    rope_kernel<<<(TOK*NH*64 + 255)/256, 256>>>(qb, pos, NH, TOK*NH*64);
    rope_split_kernel<<<(TOK*NKV*64 + 255)/256, 256>>>(kb, pos, kh, kl, NKV, TOK*NKV*64);
    split_bf16_kernel<<<((size_t)TOK*KVD + 255)/256, 256>>>(vb, vh, vl, TOK*KVD);

    // Flash attention -> split bf16 output
    flash_attn_mma<<<dim3(SEQ/128, BATCH*NH), 256, FA_SMEM>>>(qb, kh, kl, vh, vl, ah, al);

    // O projection
    gemm_nt_split<<<dim3(HID/128, TOK/128), 256, GEMM_SMEM>>>(ah, al, woh, wol, out, HID, QD);
}